// round 9
// baseline (speedup 1.0000x reference)
#include <cuda_runtime.h>
#include <cuda_bf16.h>
#include <cstdint>

// Problem constants
#define Bsz   8
#define CIN   256
#define COUT  256
#define Hh    64
#define Ww    64
#define HW    (Hh*Ww)          // 4096
#define KK    9                // 3x3 taps
#define KDIM  (CIN*KK)         // 2304
#define OFFC  18
#define EPSBN 1e-5f

// ---------------- device scratch ----------------
__device__ __nv_bfloat16 g_sh[(size_t)Bsz * KDIM * HW];   // sampled bf16 hi, [b][k][n]
__device__ __nv_bfloat16 g_sl[(size_t)Bsz * KDIM * HW];   // sampled bf16 lo
__device__ __nv_bfloat16 g_wh[(size_t)COUT * KDIM];       // weights bf16 hi, [m][k]
__device__ __nv_bfloat16 g_wl[(size_t)COUT * KDIM];       // weights bf16 lo
__device__ short4 g_sidx[Bsz * KK * HW];
__device__ float4 g_swt [Bsz * KK * HW];
__device__ float  g_conv[(size_t)Bsz * COUT * HW];        // pre-BN conv output
__device__ float  g_scale[COUT];
__device__ float  g_shift[COUT];

// ---------------- helpers ----------------
__device__ __forceinline__ uint32_t smem_u32(const void* p) {
    uint32_t a;
    asm("{ .reg .u64 t; cvta.to.shared.u64 t, %1; cvt.u32.u64 %0, t; }" : "=r"(a) : "l"(p));
    return a;
}
__device__ __forceinline__ void cp16(uint32_t dst, const void* src) {
    asm volatile("cp.async.cg.shared.global [%0], [%1], 16;" :: "r"(dst), "l"(src));
}
#define CP_COMMIT() asm volatile("cp.async.commit_group;" ::: "memory")
#define CP_WAIT1()  asm volatile("cp.async.wait_group 1;" ::: "memory")

#define LDSM_X4(r0,r1,r2,r3,addr) \
    asm volatile("ldmatrix.sync.aligned.m8n8.x4.shared.b16 {%0,%1,%2,%3}, [%4];" \
        : "=r"(r0),"=r"(r1),"=r"(r2),"=r"(r3) : "r"(addr))
#define LDSM_X4T(r0,r1,r2,r3,addr) \
    asm volatile("ldmatrix.sync.aligned.m8n8.x4.trans.shared.b16 {%0,%1,%2,%3}, [%4];" \
        : "=r"(r0),"=r"(r1),"=r"(r2),"=r"(r3) : "r"(addr))

#define MMA_BF16(d, a, b) \
    asm volatile("mma.sync.aligned.m16n8k16.row.col.f32.bf16.bf16.f32 " \
        "{%0,%1,%2,%3}, {%4,%5,%6,%7}, {%8,%9}, {%0,%1,%2,%3};" \
        : "+f"((d)[0]),"+f"((d)[1]),"+f"((d)[2]),"+f"((d)[3]) \
        : "r"((a)[0]),"r"((a)[1]),"r"((a)[2]),"r"((a)[3]), "r"((b)[0]),"r"((b)[1]))

// ============================================================================
// Kernel 0: split W into bf16 hi/lo
// ============================================================================
__global__ __launch_bounds__(256)
void wsplit_kernel(const float* __restrict__ w)
{
    int i = blockIdx.x * 256 + threadIdx.x;
    if (i < COUT * KDIM) {
        float v = w[i];
        __nv_bfloat16 h = __float2bfloat16(v);
        g_wh[i] = h;
        g_wl[i] = __float2bfloat16(v - __bfloat162float(h));
    }
}

// ============================================================================
// Kernel 1: offset conv (3x3, pad 1, Cin=256 -> 18) + bilinear descriptors
// ============================================================================
__global__ __launch_bounds__(256)
void offset_conv_kernel(const float* __restrict__ x,
                        const float* __restrict__ w_off,
                        const float* __restrict__ b_off)
{
    const int b  = blockIdx.z;
    const int bx = blockIdx.x * 16;
    const int by = blockIdx.y * 16;
    const int tx = threadIdx.x & 15;
    const int ty = threadIdx.x >> 4;
    const int px = bx + tx;
    const int py = by + ty;

    __shared__ float sx[16][18*18];
    __shared__ float sw[16*9][20];

    float acc[OFFC];
#pragma unroll
    for (int o = 0; o < OFFC; o++) acc[o] = 0.f;

    for (int c0 = 0; c0 < CIN; c0 += 16) {
        __syncthreads();
        for (int i = threadIdx.x; i < 16*18*18; i += 256) {
            int c   = i / 324;
            int rem = i % 324;
            int yy  = rem / 18 - 1 + by;
            int xx  = rem % 18 - 1 + bx;
            float v = 0.f;
            if (yy >= 0 && yy < Hh && xx >= 0 && xx < Ww)
                v = x[(((size_t)b*CIN + c0 + c)*Hh + yy)*Ww + xx];
            sx[c][rem] = v;
        }
        for (int i = threadIdx.x; i < OFFC*16*9; i += 256) {
            int o  = i % OFFC;
            int ct = i / OFFC;
            int c  = ct / 9;
            int t  = ct % 9;
            sw[c*9 + t][o] = w_off[((size_t)o*CIN + c0 + c)*9 + t];
        }
        __syncthreads();

#pragma unroll 2
        for (int c = 0; c < 16; c++) {
#pragma unroll
            for (int t = 0; t < 9; t++) {
                float xv = sx[c][(ty + t/3)*18 + (tx + t%3)];
                const float* wr = &sw[c*9 + t][0];
                float4 a0 = *(const float4*)(wr);
                float4 a1 = *(const float4*)(wr + 4);
                float4 a2 = *(const float4*)(wr + 8);
                float4 a3 = *(const float4*)(wr + 12);
                float2 a4 = *(const float2*)(wr + 16);
                acc[0]  += xv*a0.x; acc[1]  += xv*a0.y; acc[2]  += xv*a0.z; acc[3]  += xv*a0.w;
                acc[4]  += xv*a1.x; acc[5]  += xv*a1.y; acc[6]  += xv*a1.z; acc[7]  += xv*a1.w;
                acc[8]  += xv*a2.x; acc[9]  += xv*a2.y; acc[10] += xv*a2.z; acc[11] += xv*a2.w;
                acc[12] += xv*a3.x; acc[13] += xv*a3.y; acc[14] += xv*a3.z; acc[15] += xv*a3.w;
                acc[16] += xv*a4.x; acc[17] += xv*a4.y;
            }
        }
    }

#pragma unroll
    for (int kk = 0; kk < KK; kk++) {
        float dy = acc[2*kk + 0] + b_off[2*kk + 0];
        float dx = acc[2*kk + 1] + b_off[2*kk + 1];
        float pyf = (float)(kk/3 - 1) + (float)py + dy;
        float pxf = (float)(kk%3 - 1) + (float)px + dx;
        float y0f = floorf(pyf);
        float x0f = floorf(pxf);
        float fy = pyf - y0f;
        float fx = pxf - x0f;
        int iy0 = (int)y0f, ix0 = (int)x0f;
        int iy1 = iy0 + 1,  ix1 = ix0 + 1;
        bool vy0 = (iy0 >= 0) && (iy0 <= Hh-1);
        bool vy1 = (iy1 >= 0) && (iy1 <= Hh-1);
        bool vx0 = (ix0 >= 0) && (ix0 <= Ww-1);
        bool vx1 = (ix1 >= 0) && (ix1 <= Ww-1);
        float w00 = (1.f-fy)*(1.f-fx) * (float)(vy0 && vx0);
        float w01 = (1.f-fy)*fx       * (float)(vy0 && vx1);
        float w10 = fy*(1.f-fx)       * (float)(vy1 && vx0);
        float w11 = fy*fx             * (float)(vy1 && vx1);
        int cy0 = min(max(iy0, 0), Hh-1);
        int cy1 = min(max(iy1, 0), Hh-1);
        int cx0 = min(max(ix0, 0), Ww-1);
        int cx1 = min(max(ix1, 0), Ww-1);
        int s = (b*KK + kk)*HW + py*Ww + px;
        g_sidx[s] = make_short4((short)(cy0*Ww + cx0), (short)(cy0*Ww + cx1),
                                (short)(cy1*Ww + cx0), (short)(cy1*Ww + cx1));
        g_swt[s]  = make_float4(w00, w01, w10, w11);
    }
}

// ============================================================================
// Kernel 2: gather -> sampled matrix split to bf16 hi/lo, layout [b][k][n]
// ============================================================================
__global__ __launch_bounds__(256)
void gather_kernel(const float* __restrict__ x)
{
    const int p  = blockIdx.x * 256 + threadIdx.x;  // 0..4095
    const int kk = blockIdx.y;
    const int b  = blockIdx.z;

    const int s = (b*KK + kk)*HW + p;
    const short4 si = g_sidx[s];
    const float4 wv = g_swt[s];
    const int i0 = si.x, i1 = si.y, i2 = si.z, i3 = si.w;

    const float* xb = x + (size_t)b*CIN*HW;
    __nv_bfloat16* oh = g_sh + ((size_t)b*KDIM + kk)*HW + p;
    __nv_bfloat16* ol = g_sl + ((size_t)b*KDIM + kk)*HW + p;

#pragma unroll 4
    for (int c = 0; c < CIN; c++) {
        const float* xp = xb + (size_t)c*HW;
        float v = wv.x*__ldg(xp + i0) + wv.y*__ldg(xp + i1)
                + wv.z*__ldg(xp + i2) + wv.w*__ldg(xp + i3);
        __nv_bfloat16 h = __float2bfloat16(v);
        float r = v - __bfloat162float(h);
        oh[(size_t)c*KK*HW] = h;
        ol[(size_t)c*KK*HW] = __float2bfloat16(r);
    }
}

// ============================================================================
// Kernel 3: mma.sync bf16x3 GEMM: C[256,4096] = W[256,2304] * S[2304,4096]
// CTA 128x128, BK=32, 8 warps (4x2), warp tile 32x64, cp.async double buffer.
// ============================================================================
#define BM 128
#define BN 128
#define BK 32
#define LDA 40                     // A smem row pitch in bf16 (80B, conflict-free ldmatrix)
#define LDB 136                    // B smem row pitch in bf16 (272B, conflict-free trans)
#define A_TILE (BM*LDA*2)          // 10240 B
#define B_TILE (BK*LDB*2)          // 8704 B
#define STAGE  (2*A_TILE + 2*B_TILE)   // 37888 B
#define GEMM_SMEM (2*STAGE)            // 75776 B
#define NCH (KDIM/BK)              // 72

__device__ __forceinline__ void load_chunk(uint32_t sstage,
    const __nv_bfloat16* __restrict__ Wh, const __nv_bfloat16* __restrict__ Wl,
    const __nv_bfloat16* __restrict__ Sh, const __nv_bfloat16* __restrict__ Sl,
    int k0, int tid)
{
    // A: 128 rows x 32 bf16 (64B) => 4 x 16B segs per row
#pragma unroll
    for (int it = 0; it < 2; it++) {
        int idx = it*256 + tid;
        int row = idx >> 2, seg = idx & 3;
        uint32_t dst = sstage + (uint32_t)(row*(LDA*2) + seg*16);
        const __nv_bfloat16* sa = Wh + (size_t)row*KDIM + k0 + seg*8;
        const __nv_bfloat16* sb = Wl + (size_t)row*KDIM + k0 + seg*8;
        cp16(dst, sa);
        cp16(dst + A_TILE, sb);
    }
    // B: 32 rows x 128 bf16 (256B) => 16 x 16B segs per row
#pragma unroll
    for (int it = 0; it < 2; it++) {
        int idx = it*256 + tid;
        int row = idx >> 4, seg = idx & 15;
        uint32_t dst = sstage + 2*A_TILE + (uint32_t)(row*(LDB*2) + seg*16);
        const __nv_bfloat16* sa = Sh + (size_t)(k0+row)*HW + seg*8;
        const __nv_bfloat16* sb = Sl + (size_t)(k0+row)*HW + seg*8;
        cp16(dst, sa);
        cp16(dst + B_TILE, sb);
    }
}

__global__ __launch_bounds__(256)
void gemm_mma_kernel(const float* __restrict__ bias)
{
    extern __shared__ char smem[];
    const uint32_t sb = smem_u32(smem);
    const int tid  = threadIdx.x;
    const int lane = tid & 31;
    const int wid  = tid >> 5;
    const int wm   = wid & 3;      // 4 warps along M (32 rows each)
    const int wn   = wid >> 2;     // 2 warps along N (64 cols each)
    const int b     = blockIdx.z;
    const int mbase = blockIdx.y * BM;
    const int nbase = blockIdx.x * BN;

    const __nv_bfloat16* __restrict__ Wh = g_wh + (size_t)mbase*KDIM;
    const __nv_bfloat16* __restrict__ Wl = g_wl + (size_t)mbase*KDIM;
    const __nv_bfloat16* __restrict__ Sh = g_sh + (size_t)b*KDIM*HW + nbase;
    const __nv_bfloat16* __restrict__ Sl = g_sl + (size_t)b*KDIM*HW + nbase;

    float acc[2][8][4];
#pragma unroll
    for (int mi = 0; mi < 2; mi++)
#pragma unroll
        for (int ni = 0; ni < 8; ni++)
#pragma unroll
            for (int r = 0; r < 4; r++) acc[mi][ni][r] = 0.f;

    // prologue: chunk 0 -> stage 0
    load_chunk(sb, Wh, Wl, Sh, Sl, 0, tid);
    CP_COMMIT();

    // precomputed intra-fragment offsets
    const uint32_t a_lane_off = (uint32_t)((wm*32 + (lane & 15))*LDA + ((lane >> 4) << 3)) * 2;
    const uint32_t b_lane_off = (uint32_t)(((lane & 7) + ((lane >> 3) & 1)*8)*LDB
                                           + wn*64 + ((lane >> 4) << 3)) * 2;

    for (int i = 0; i < NCH; i++) {
        if (i + 1 < NCH)
            load_chunk(sb + ((i+1)&1)*STAGE, Wh, Wl, Sh, Sl, (i+1)*BK, tid);
        CP_COMMIT();
        CP_WAIT1();
        __syncthreads();

        const uint32_t st  = sb + (i&1)*STAGE;
        const uint32_t a_h = st;
        const uint32_t a_l = st + A_TILE;
        const uint32_t b_h = st + 2*A_TILE;
        const uint32_t b_l = st + 2*A_TILE + B_TILE;

#pragma unroll
        for (int ks = 0; ks < 2; ks++) {
            uint32_t ah[2][4], al[2][4], bh[8][2], bl[8][2];
            uint32_t aoff = a_lane_off + ks*32;          // +16 bf16 in k
            LDSM_X4(ah[0][0],ah[0][1],ah[0][2],ah[0][3], a_h + aoff);
            LDSM_X4(ah[1][0],ah[1][1],ah[1][2],ah[1][3], a_h + aoff + 16*(LDA*2));
            LDSM_X4(al[0][0],al[0][1],al[0][2],al[0][3], a_l + aoff);
            LDSM_X4(al[1][0],al[1][1],al[1][2],al[1][3], a_l + aoff + 16*(LDA*2));

            uint32_t boff = b_lane_off + ks*16*(LDB*2);  // +16 k-rows
#pragma unroll
            for (int q = 0; q < 4; q++) {
                LDSM_X4T(bh[2*q][0],bh[2*q][1],bh[2*q+1][0],bh[2*q+1][1], b_h + boff + q*32);
                LDSM_X4T(bl[2*q][0],bl[2*q][1],bl[2*q+1][0],bl[2*q+1][1], b_l + boff + q*32);
            }

#pragma unroll
            for (int mi = 0; mi < 2; mi++)
#pragma unroll
                for (int ni = 0; ni < 8; ni++) {
                    MMA_BF16(acc[mi][ni], ah[mi], bh[ni]);
                    MMA_BF16(acc[mi][ni], ah[mi], bl[ni]);
                    MMA_BF16(acc[mi][ni], al[mi], bh[ni]);
                }
        }
        __syncthreads();
    }

    // epilogue: + bias, store to g_conv
    float* Cb = g_conv + (size_t)b*COUT*HW;
#pragma unroll
    for (int mi = 0; mi < 2; mi++) {
        int m0 = mbase + wm*32 + mi*16 + (lane >> 2);
        float bv0 = bias[m0];
        float bv1 = bias[m0 + 8];
#pragma unroll
        for (int ni = 0; ni < 8; ni++) {
            int n = nbase + wn*64 + ni*8 + (lane & 3)*2;
            float2 v0, v1;
            v0.x = acc[mi][ni][0] + bv0; v0.y = acc[mi][ni][1] + bv0;
            v1.x = acc[mi][ni][2] + bv1; v1.y = acc[mi][ni][3] + bv1;
            *(float2*)&Cb[(size_t)m0*HW + n]       = v0;
            *(float2*)&Cb[(size_t)(m0+8)*HW + n]   = v1;
        }
    }
}

// ============================================================================
// Kernel 4: per-channel BN stats (fp32, vectorized)
// ============================================================================
__global__ __launch_bounds__(256)
void bn_stats_kernel(const float* __restrict__ gamma,
                     const float* __restrict__ beta)
{
    const int o = blockIdx.x;
    float s = 0.f, s2 = 0.f;
    for (int bb = 0; bb < Bsz; bb++) {
        const float4* base = (const float4*)(g_conv + ((size_t)(bb*COUT + o))*HW);
        for (int i = threadIdx.x; i < HW/4; i += 256) {
            float4 v = base[i];
            s  += v.x + v.y + v.z + v.w;
            s2 += v.x*v.x + v.y*v.y + v.z*v.z + v.w*v.w;
        }
    }
    __shared__ float sh0[256];
    __shared__ float sh1[256];
    sh0[threadIdx.x] = s;
    sh1[threadIdx.x] = s2;
    __syncthreads();
    for (int st = 128; st > 0; st >>= 1) {
        if (threadIdx.x < st) {
            sh0[threadIdx.x] += sh0[threadIdx.x + st];
            sh1[threadIdx.x] += sh1[threadIdx.x + st];
        }
        __syncthreads();
    }
    if (threadIdx.x == 0) {
        float n = (float)(Bsz*HW);
        float mean = sh0[0] / n;
        float var  = sh1[0] / n - mean*mean;
        float sc = gamma[o] * rsqrtf(var + EPSBN);
        g_scale[o] = sc;
        g_shift[o] = beta[o] - mean * sc;
    }
}

// ============================================================================
// Kernel 5: normalize + ReLU -> final output
// ============================================================================
__global__ __launch_bounds__(256)
void bn_apply_kernel(float* __restrict__ out)
{
    size_t e = (size_t)blockIdx.x * 256 + threadIdx.x;
    size_t f = e * 4;
    int o = (int)((f >> 12) & (COUT - 1));
    float4 v = *(const float4*)(g_conv + f);
    float sc = g_scale[o], sh = g_shift[o];
    v.x = fmaxf(v.x*sc + sh, 0.f);
    v.y = fmaxf(v.y*sc + sh, 0.f);
    v.z = fmaxf(v.z*sc + sh, 0.f);
    v.w = fmaxf(v.w*sc + sh, 0.f);
    *(float4*)(out + f) = v;
}

// ============================================================================
extern "C" void kernel_launch(void* const* d_in, const int* in_sizes, int n_in,
                              void* d_out, int out_size)
{
    const float* x     = (const float*)d_in[0];
    const float* w_off = (const float*)d_in[1];
    const float* b_off = (const float*)d_in[2];
    const float* w     = (const float*)d_in[3];
    const float* bias  = (const float*)d_in[4];
    const float* gamma = (const float*)d_in[5];
    const float* beta  = (const float*)d_in[6];
    float* out = (float*)d_out;

    cudaFuncSetAttribute(gemm_mma_kernel,
                         cudaFuncAttributeMaxDynamicSharedMemorySize, GEMM_SMEM);

    wsplit_kernel<<<(COUT*KDIM + 255)/256, 256>>>(w);
    offset_conv_kernel<<<dim3(4, 4, Bsz), 256>>>(x, w_off, b_off);
    gather_kernel<<<dim3(HW/256, KK, Bsz), 256>>>(x);
    gemm_mma_kernel<<<dim3(HW/BN, COUT/BM, Bsz), 256, GEMM_SMEM>>>(bias);
    bn_stats_kernel<<<COUT, 256>>>(gamma, beta);
    bn_apply_kernel<<<(Bsz*COUT*HW)/(256*4), 256>>>(out);
}

// round 10
// speedup vs baseline: 1.0024x; 1.0024x over previous
#include <cuda_runtime.h>
#include <cuda_bf16.h>
#include <cstdint>

// Problem constants
#define Bsz   8
#define CIN   256
#define COUT  256
#define Hh    64
#define Ww    64
#define HW    (Hh*Ww)          // 4096
#define KK    9                // 3x3 taps
#define KDIM  (CIN*KK)         // 2304
#define OFFC  18
#define EPSBN 1e-5f

// ---------------- device scratch ----------------
__device__ __nv_bfloat16 g_sh[(size_t)Bsz * KDIM * HW];   // sampled bf16 hi, [b][k][n]
__device__ __nv_bfloat16 g_sl[(size_t)Bsz * KDIM * HW];   // sampled bf16 lo
__device__ __nv_bfloat16 g_wh[(size_t)COUT * KDIM];       // weights bf16 hi, [m][k]
__device__ __nv_bfloat16 g_wl[(size_t)COUT * KDIM];       // weights bf16 lo
__device__ short4 g_sidx[Bsz * KK * HW];
__device__ float4 g_swt [Bsz * KK * HW];
__device__ float  g_conv[(size_t)Bsz * COUT * HW];        // pre-BN conv output
__device__ float  g_scale[COUT];
__device__ float  g_shift[COUT];

// ---------------- helpers ----------------
__device__ __forceinline__ uint32_t smem_u32(const void* p) {
    uint32_t a;
    asm("{ .reg .u64 t; cvta.to.shared.u64 t, %1; cvt.u32.u64 %0, t; }" : "=r"(a) : "l"(p));
    return a;
}
__device__ __forceinline__ void cp16(uint32_t dst, const void* src) {
    asm volatile("cp.async.cg.shared.global [%0], [%1], 16;" :: "r"(dst), "l"(src));
}
#define CP_COMMIT() asm volatile("cp.async.commit_group;" ::: "memory")
#define CP_WAIT1()  asm volatile("cp.async.wait_group 1;" ::: "memory")

#define LDSM_X4(r0,r1,r2,r3,addr) \
    asm volatile("ldmatrix.sync.aligned.m8n8.x4.shared.b16 {%0,%1,%2,%3}, [%4];" \
        : "=r"(r0),"=r"(r1),"=r"(r2),"=r"(r3) : "r"(addr))
#define LDSM_X4T(r0,r1,r2,r3,addr) \
    asm volatile("ldmatrix.sync.aligned.m8n8.x4.trans.shared.b16 {%0,%1,%2,%3}, [%4];" \
        : "=r"(r0),"=r"(r1),"=r"(r2),"=r"(r3) : "r"(addr))

#define MMA_BF16(d, a, b) \
    asm volatile("mma.sync.aligned.m16n8k16.row.col.f32.bf16.bf16.f32 " \
        "{%0,%1,%2,%3}, {%4,%5,%6,%7}, {%8,%9}, {%0,%1,%2,%3};" \
        : "+f"((d)[0]),"+f"((d)[1]),"+f"((d)[2]),"+f"((d)[3]) \
        : "r"((a)[0]),"r"((a)[1]),"r"((a)[2]),"r"((a)[3]), "r"((b)[0]),"r"((b)[1]))

// ============================================================================
// Kernel 0: split W into bf16 hi/lo
// ============================================================================
__global__ __launch_bounds__(256)
void wsplit_kernel(const float* __restrict__ w)
{
    int i = blockIdx.x * 256 + threadIdx.x;
    if (i < COUT * KDIM) {
        float v = w[i];
        __nv_bfloat16 h = __float2bfloat16(v);
        g_wh[i] = h;
        g_wl[i] = __float2bfloat16(v - __bfloat162float(h));
    }
}

// ============================================================================
// Kernel 1: offset conv (3x3, pad 1, Cin=256 -> 18) + bilinear descriptors
// ============================================================================
__global__ __launch_bounds__(256)
void offset_conv_kernel(const float* __restrict__ x,
                        const float* __restrict__ w_off,
                        const float* __restrict__ b_off)
{
    const int b  = blockIdx.z;
    const int bx = blockIdx.x * 16;
    const int by = blockIdx.y * 16;
    const int tx = threadIdx.x & 15;
    const int ty = threadIdx.x >> 4;
    const int px = bx + tx;
    const int py = by + ty;

    __shared__ float sx[16][18*18];
    __shared__ float sw[16*9][20];

    float acc[OFFC];
#pragma unroll
    for (int o = 0; o < OFFC; o++) acc[o] = 0.f;

    for (int c0 = 0; c0 < CIN; c0 += 16) {
        __syncthreads();
        for (int i = threadIdx.x; i < 16*18*18; i += 256) {
            int c   = i / 324;
            int rem = i % 324;
            int yy  = rem / 18 - 1 + by;
            int xx  = rem % 18 - 1 + bx;
            float v = 0.f;
            if (yy >= 0 && yy < Hh && xx >= 0 && xx < Ww)
                v = x[(((size_t)b*CIN + c0 + c)*Hh + yy)*Ww + xx];
            sx[c][rem] = v;
        }
        for (int i = threadIdx.x; i < OFFC*16*9; i += 256) {
            int o  = i % OFFC;
            int ct = i / OFFC;
            int c  = ct / 9;
            int t  = ct % 9;
            sw[c*9 + t][o] = w_off[((size_t)o*CIN + c0 + c)*9 + t];
        }
        __syncthreads();

#pragma unroll 2
        for (int c = 0; c < 16; c++) {
#pragma unroll
            for (int t = 0; t < 9; t++) {
                float xv = sx[c][(ty + t/3)*18 + (tx + t%3)];
                const float* wr = &sw[c*9 + t][0];
                float4 a0 = *(const float4*)(wr);
                float4 a1 = *(const float4*)(wr + 4);
                float4 a2 = *(const float4*)(wr + 8);
                float4 a3 = *(const float4*)(wr + 12);
                float2 a4 = *(const float2*)(wr + 16);
                acc[0]  += xv*a0.x; acc[1]  += xv*a0.y; acc[2]  += xv*a0.z; acc[3]  += xv*a0.w;
                acc[4]  += xv*a1.x; acc[5]  += xv*a1.y; acc[6]  += xv*a1.z; acc[7]  += xv*a1.w;
                acc[8]  += xv*a2.x; acc[9]  += xv*a2.y; acc[10] += xv*a2.z; acc[11] += xv*a2.w;
                acc[12] += xv*a3.x; acc[13] += xv*a3.y; acc[14] += xv*a3.z; acc[15] += xv*a3.w;
                acc[16] += xv*a4.x; acc[17] += xv*a4.y;
            }
        }
    }

#pragma unroll
    for (int kk = 0; kk < KK; kk++) {
        float dy = acc[2*kk + 0] + b_off[2*kk + 0];
        float dx = acc[2*kk + 1] + b_off[2*kk + 1];
        float pyf = (float)(kk/3 - 1) + (float)py + dy;
        float pxf = (float)(kk%3 - 1) + (float)px + dx;
        float y0f = floorf(pyf);
        float x0f = floorf(pxf);
        float fy = pyf - y0f;
        float fx = pxf - x0f;
        int iy0 = (int)y0f, ix0 = (int)x0f;
        int iy1 = iy0 + 1,  ix1 = ix0 + 1;
        bool vy0 = (iy0 >= 0) && (iy0 <= Hh-1);
        bool vy1 = (iy1 >= 0) && (iy1 <= Hh-1);
        bool vx0 = (ix0 >= 0) && (ix0 <= Ww-1);
        bool vx1 = (ix1 >= 0) && (ix1 <= Ww-1);
        float w00 = (1.f-fy)*(1.f-fx) * (float)(vy0 && vx0);
        float w01 = (1.f-fy)*fx       * (float)(vy0 && vx1);
        float w10 = fy*(1.f-fx)       * (float)(vy1 && vx0);
        float w11 = fy*fx             * (float)(vy1 && vx1);
        int cy0 = min(max(iy0, 0), Hh-1);
        int cy1 = min(max(iy1, 0), Hh-1);
        int cx0 = min(max(ix0, 0), Ww-1);
        int cx1 = min(max(ix1, 0), Ww-1);
        int s = (b*KK + kk)*HW + py*Ww + px;
        g_sidx[s] = make_short4((short)(cy0*Ww + cx0), (short)(cy0*Ww + cx1),
                                (short)(cy1*Ww + cx0), (short)(cy1*Ww + cx1));
        g_swt[s]  = make_float4(w00, w01, w10, w11);
    }
}

// ============================================================================
// Kernel 2: gather -> sampled matrix split to bf16 hi/lo, layout [b][k][n]
// ============================================================================
__global__ __launch_bounds__(256)
void gather_kernel(const float* __restrict__ x)
{
    const int p  = blockIdx.x * 256 + threadIdx.x;  // 0..4095
    const int kk = blockIdx.y;
    const int b  = blockIdx.z;

    const int s = (b*KK + kk)*HW + p;
    const short4 si = g_sidx[s];
    const float4 wv = g_swt[s];
    const int i0 = si.x, i1 = si.y, i2 = si.z, i3 = si.w;

    const float* xb = x + (size_t)b*CIN*HW;
    __nv_bfloat16* oh = g_sh + ((size_t)b*KDIM + kk)*HW + p;
    __nv_bfloat16* ol = g_sl + ((size_t)b*KDIM + kk)*HW + p;

#pragma unroll 4
    for (int c = 0; c < CIN; c++) {
        const float* xp = xb + (size_t)c*HW;
        float v = wv.x*__ldg(xp + i0) + wv.y*__ldg(xp + i1)
                + wv.z*__ldg(xp + i2) + wv.w*__ldg(xp + i3);
        __nv_bfloat16 h = __float2bfloat16(v);
        float r = v - __bfloat162float(h);
        oh[(size_t)c*KK*HW] = h;
        ol[(size_t)c*KK*HW] = __float2bfloat16(r);
    }
}

// ============================================================================
// Kernel 3: mma.sync bf16x3 GEMM: C[256,4096] = W[256,2304] * S[2304,4096]
// CTA 128x128, BK=32, 8 warps (4x2), warp tile 32x64, cp.async double buffer.
// ============================================================================
#define BM 128
#define BN 128
#define BK 32
#define LDA 40                     // A smem row pitch in bf16 (80B, conflict-free ldmatrix)
#define LDB 136                    // B smem row pitch in bf16 (272B, conflict-free trans)
#define A_TILE (BM*LDA*2)          // 10240 B
#define B_TILE (BK*LDB*2)          // 8704 B
#define STAGE  (2*A_TILE + 2*B_TILE)   // 37888 B
#define GEMM_SMEM (2*STAGE)            // 75776 B
#define NCH (KDIM/BK)              // 72

__device__ __forceinline__ void load_chunk(uint32_t sstage,
    const __nv_bfloat16* __restrict__ Wh, const __nv_bfloat16* __restrict__ Wl,
    const __nv_bfloat16* __restrict__ Sh, const __nv_bfloat16* __restrict__ Sl,
    int k0, int tid)
{
    // A: 128 rows x 32 bf16 (64B) => 4 x 16B segs per row
#pragma unroll
    for (int it = 0; it < 2; it++) {
        int idx = it*256 + tid;
        int row = idx >> 2, seg = idx & 3;
        uint32_t dst = sstage + (uint32_t)(row*(LDA*2) + seg*16);
        const __nv_bfloat16* sa = Wh + (size_t)row*KDIM + k0 + seg*8;
        const __nv_bfloat16* sb = Wl + (size_t)row*KDIM + k0 + seg*8;
        cp16(dst, sa);
        cp16(dst + A_TILE, sb);
    }
    // B: 32 rows x 128 bf16 (256B) => 16 x 16B segs per row
#pragma unroll
    for (int it = 0; it < 2; it++) {
        int idx = it*256 + tid;
        int row = idx >> 4, seg = idx & 15;
        uint32_t dst = sstage + 2*A_TILE + (uint32_t)(row*(LDB*2) + seg*16);
        const __nv_bfloat16* sa = Sh + (size_t)(k0+row)*HW + seg*8;
        const __nv_bfloat16* sb = Sl + (size_t)(k0+row)*HW + seg*8;
        cp16(dst, sa);
        cp16(dst + B_TILE, sb);
    }
}

__global__ __launch_bounds__(256)
void gemm_mma_kernel(const float* __restrict__ bias)
{
    extern __shared__ char smem[];
    const uint32_t sb = smem_u32(smem);
    const int tid  = threadIdx.x;
    const int lane = tid & 31;
    const int wid  = tid >> 5;
    const int wm   = wid & 3;      // 4 warps along M (32 rows each)
    const int wn   = wid >> 2;     // 2 warps along N (64 cols each)
    const int b     = blockIdx.z;
    const int mbase = blockIdx.y * BM;
    const int nbase = blockIdx.x * BN;

    const __nv_bfloat16* __restrict__ Wh = g_wh + (size_t)mbase*KDIM;
    const __nv_bfloat16* __restrict__ Wl = g_wl + (size_t)mbase*KDIM;
    const __nv_bfloat16* __restrict__ Sh = g_sh + (size_t)b*KDIM*HW + nbase;
    const __nv_bfloat16* __restrict__ Sl = g_sl + (size_t)b*KDIM*HW + nbase;

    float acc[2][8][4];
#pragma unroll
    for (int mi = 0; mi < 2; mi++)
#pragma unroll
        for (int ni = 0; ni < 8; ni++)
#pragma unroll
            for (int r = 0; r < 4; r++) acc[mi][ni][r] = 0.f;

    // prologue: chunk 0 -> stage 0
    load_chunk(sb, Wh, Wl, Sh, Sl, 0, tid);
    CP_COMMIT();

    // precomputed intra-fragment offsets
    const uint32_t a_lane_off = (uint32_t)((wm*32 + (lane & 15))*LDA + ((lane >> 4) << 3)) * 2;
    const uint32_t b_lane_off = (uint32_t)(((lane & 7) + ((lane >> 3) & 1)*8)*LDB
                                           + wn*64 + ((lane >> 4) << 3)) * 2;

    for (int i = 0; i < NCH; i++) {
        if (i + 1 < NCH)
            load_chunk(sb + ((i+1)&1)*STAGE, Wh, Wl, Sh, Sl, (i+1)*BK, tid);
        CP_COMMIT();
        CP_WAIT1();
        __syncthreads();

        const uint32_t st  = sb + (i&1)*STAGE;
        const uint32_t a_h = st;
        const uint32_t a_l = st + A_TILE;
        const uint32_t b_h = st + 2*A_TILE;
        const uint32_t b_l = st + 2*A_TILE + B_TILE;

#pragma unroll
        for (int ks = 0; ks < 2; ks++) {
            uint32_t ah[2][4], al[2][4], bh[8][2], bl[8][2];
            uint32_t aoff = a_lane_off + ks*32;          // +16 bf16 in k
            LDSM_X4(ah[0][0],ah[0][1],ah[0][2],ah[0][3], a_h + aoff);
            LDSM_X4(ah[1][0],ah[1][1],ah[1][2],ah[1][3], a_h + aoff + 16*(LDA*2));
            LDSM_X4(al[0][0],al[0][1],al[0][2],al[0][3], a_l + aoff);
            LDSM_X4(al[1][0],al[1][1],al[1][2],al[1][3], a_l + aoff + 16*(LDA*2));

            uint32_t boff = b_lane_off + ks*16*(LDB*2);  // +16 k-rows
#pragma unroll
            for (int q = 0; q < 4; q++) {
                LDSM_X4T(bh[2*q][0],bh[2*q][1],bh[2*q+1][0],bh[2*q+1][1], b_h + boff + q*32);
                LDSM_X4T(bl[2*q][0],bl[2*q][1],bl[2*q+1][0],bl[2*q+1][1], b_l + boff + q*32);
            }

#pragma unroll
            for (int mi = 0; mi < 2; mi++)
#pragma unroll
                for (int ni = 0; ni < 8; ni++) {
                    MMA_BF16(acc[mi][ni], ah[mi], bh[ni]);
                    MMA_BF16(acc[mi][ni], ah[mi], bl[ni]);
                    MMA_BF16(acc[mi][ni], al[mi], bh[ni]);
                }
        }
        __syncthreads();
    }

    // epilogue: + bias, store to g_conv
    float* Cb = g_conv + (size_t)b*COUT*HW;
#pragma unroll
    for (int mi = 0; mi < 2; mi++) {
        int m0 = mbase + wm*32 + mi*16 + (lane >> 2);
        float bv0 = bias[m0];
        float bv1 = bias[m0 + 8];
#pragma unroll
        for (int ni = 0; ni < 8; ni++) {
            int n = nbase + wn*64 + ni*8 + (lane & 3)*2;
            float2 v0, v1;
            v0.x = acc[mi][ni][0] + bv0; v0.y = acc[mi][ni][1] + bv0;
            v1.x = acc[mi][ni][2] + bv1; v1.y = acc[mi][ni][3] + bv1;
            *(float2*)&Cb[(size_t)m0*HW + n]       = v0;
            *(float2*)&Cb[(size_t)(m0+8)*HW + n]   = v1;
        }
    }
}

// ============================================================================
// Kernel 4: per-channel BN stats (fp32, vectorized)
// ============================================================================
__global__ __launch_bounds__(256)
void bn_stats_kernel(const float* __restrict__ gamma,
                     const float* __restrict__ beta)
{
    const int o = blockIdx.x;
    float s = 0.f, s2 = 0.f;
    for (int bb = 0; bb < Bsz; bb++) {
        const float4* base = (const float4*)(g_conv + ((size_t)(bb*COUT + o))*HW);
        for (int i = threadIdx.x; i < HW/4; i += 256) {
            float4 v = base[i];
            s  += v.x + v.y + v.z + v.w;
            s2 += v.x*v.x + v.y*v.y + v.z*v.z + v.w*v.w;
        }
    }
    __shared__ float sh0[256];
    __shared__ float sh1[256];
    sh0[threadIdx.x] = s;
    sh1[threadIdx.x] = s2;
    __syncthreads();
    for (int st = 128; st > 0; st >>= 1) {
        if (threadIdx.x < st) {
            sh0[threadIdx.x] += sh0[threadIdx.x + st];
            sh1[threadIdx.x] += sh1[threadIdx.x + st];
        }
        __syncthreads();
    }
    if (threadIdx.x == 0) {
        float n = (float)(Bsz*HW);
        float mean = sh0[0] / n;
        float var  = sh1[0] / n - mean*mean;
        float sc = gamma[o] * rsqrtf(var + EPSBN);
        g_scale[o] = sc;
        g_shift[o] = beta[o] - mean * sc;
    }
}

// ============================================================================
// Kernel 5: normalize + ReLU -> final output
// ============================================================================
__global__ __launch_bounds__(256)
void bn_apply_kernel(float* __restrict__ out)
{
    size_t e = (size_t)blockIdx.x * 256 + threadIdx.x;
    size_t f = e * 4;
    int o = (int)((f >> 12) & (COUT - 1));
    float4 v = *(const float4*)(g_conv + f);
    float sc = g_scale[o], sh = g_shift[o];
    v.x = fmaxf(v.x*sc + sh, 0.f);
    v.y = fmaxf(v.y*sc + sh, 0.f);
    v.z = fmaxf(v.z*sc + sh, 0.f);
    v.w = fmaxf(v.w*sc + sh, 0.f);
    *(float4*)(out + f) = v;
}

// ============================================================================
extern "C" void kernel_launch(void* const* d_in, const int* in_sizes, int n_in,
                              void* d_out, int out_size)
{
    const float* x     = (const float*)d_in[0];
    const float* w_off = (const float*)d_in[1];
    const float* b_off = (const float*)d_in[2];
    const float* w     = (const float*)d_in[3];
    const float* bias  = (const float*)d_in[4];
    const float* gamma = (const float*)d_in[5];
    const float* beta  = (const float*)d_in[6];
    float* out = (float*)d_out;

    cudaFuncSetAttribute(gemm_mma_kernel,
                         cudaFuncAttributeMaxDynamicSharedMemorySize, GEMM_SMEM);

    wsplit_kernel<<<(COUT*KDIM + 255)/256, 256>>>(w);
    offset_conv_kernel<<<dim3(4, 4, Bsz), 256>>>(x, w_off, b_off);
    gather_kernel<<<dim3(HW/256, KK, Bsz), 256>>>(x);
    gemm_mma_kernel<<<dim3(HW/BN, COUT/BM, Bsz), 256, GEMM_SMEM>>>(bias);
    bn_stats_kernel<<<COUT, 256>>>(gamma, beta);
    bn_apply_kernel<<<(Bsz*COUT*HW)/(256*4), 256>>>(out);
}